// round 6
// baseline (speedup 1.0000x reference)
#include <cuda_runtime.h>
#include <cstdint>

#define BATCH 4
#define NPTS  8192
#define NSETS 8                    // index = batch*2 + side (side 0 = a, 1 = b)
#define NPT_ALL (NSETS * NPTS)     // 65536
#define G  32
#define G3 (G * G * G)

// ---- static scratch (re-initialized every launch sequence) ----
__device__ unsigned int g_bmin[3], g_bmax[3];
__device__ int    g_hist[NSETS][G3];
__device__ int    g_cellStart[NSETS][G3 + 1];
__device__ int    g_writePtr[NSETS][G3];
__device__ float4 g_sorted[NPT_ALL];        // cell-sorted points, (x,y,z,0)
__device__ float  g_acc;

// order-preserving float<->uint encoding for atomic min/max
__device__ __forceinline__ unsigned int enc(float f) {
    unsigned int u = __float_as_uint(f);
    return (u & 0x80000000u) ? ~u : (u | 0x80000000u);
}
__device__ __forceinline__ float dec(unsigned int u) {
    return __uint_as_float((u & 0x80000000u) ? (u & 0x7FFFFFFFu) : ~u);
}

struct GridP { float lox, loy, loz, inv_h, h; };
__device__ __forceinline__ GridP grid_params() {
    GridP g;
    g.lox = dec(g_bmin[0]); g.loy = dec(g_bmin[1]); g.loz = dec(g_bmin[2]);
    float ex = dec(g_bmax[0]) - g.lox;
    float ey = dec(g_bmax[1]) - g.loy;
    float ez = dec(g_bmax[2]) - g.loz;
    float e = fmaxf(ex, fmaxf(ey, ez)) * (1.0f + 1e-5f);
    g.h = e / (float)G;
    g.inv_h = (float)G / e;
    return g;
}
__device__ __forceinline__ int cclamp(int v) { return min(max(v, 0), G - 1); }

__device__ __forceinline__ const float* pt_ptr(const float* a, const float* b, int bs, int i) {
    const float* base = (bs & 1) ? b : a;
    return base + ((size_t)((bs >> 1) * NPTS + i)) * 3;
}

// ---- k0: zero hist, reset bbox sentinels + accumulator ----
__global__ void k0_init() {
    int i = blockIdx.x * blockDim.x + threadIdx.x;
    int stride = gridDim.x * blockDim.x;
    for (int j = i; j < NSETS * G3; j += stride) ((int*)g_hist)[j] = 0;
    if (i < 3) { g_bmin[i] = 0xFFFFFFFFu; g_bmax[i] = 0u; }
    if (i == 0) g_acc = 0.0f;
}

// ---- k1: global per-axis bbox over both clouds ----
__global__ void k1_bbox(const float* __restrict__ a, const float* __restrict__ b) {
    __shared__ unsigned int smin[3], smax[3];
    if (threadIdx.x < 3) { smin[threadIdx.x] = 0xFFFFFFFFu; smax[threadIdx.x] = 0u; }
    __syncthreads();
    const int total = BATCH * NPTS * 3;
    int i = blockIdx.x * blockDim.x + threadIdx.x;
    int stride = gridDim.x * blockDim.x;
    unsigned int lmin[3] = {0xFFFFFFFFu, 0xFFFFFFFFu, 0xFFFFFFFFu};
    unsigned int lmax[3] = {0u, 0u, 0u};
    for (int j = i; j < 2 * total; j += stride) {
        float v = (j < total) ? a[j] : b[j - total];
        int axis = j % 3;
        unsigned int e = enc(v);
        lmin[axis] = min(lmin[axis], e);
        lmax[axis] = max(lmax[axis], e);
    }
    #pragma unroll
    for (int ax = 0; ax < 3; ax++) {
        atomicMin(&smin[ax], lmin[ax]);
        atomicMax(&smax[ax], lmax[ax]);
    }
    __syncthreads();
    if (threadIdx.x < 3) {
        atomicMin(&g_bmin[threadIdx.x], smin[threadIdx.x]);
        atomicMax(&g_bmax[threadIdx.x], smax[threadIdx.x]);
    }
}

// ---- k2: histogram of cell occupancy ----
__global__ void k2_hist(const float* __restrict__ a, const float* __restrict__ b) {
    int idx = blockIdx.x * blockDim.x + threadIdx.x;
    if (idx >= NPT_ALL) return;
    GridP g = grid_params();
    int bs = idx >> 13, i = idx & (NPTS - 1);
    const float* p = pt_ptr(a, b, bs, i);
    int cx = cclamp((int)((p[0] - g.lox) * g.inv_h));
    int cy = cclamp((int)((p[1] - g.loy) * g.inv_h));
    int cz = cclamp((int)((p[2] - g.loz) * g.inv_h));
    atomicAdd(&g_hist[bs][(cz * G + cy) * G + cx], 1);
}

// ---- k3: exclusive scan per set (one CTA per set) ----
#define SCAN_T 1024
#define CELLS_PER_T (G3 / SCAN_T)    // 32
__global__ __launch_bounds__(SCAN_T)
void k3_scan() {
    __shared__ int sh[SCAN_T];
    int bs = blockIdx.x;
    int t = threadIdx.x;
    int base = t * CELLS_PER_T;
    int cnt[CELLS_PER_T];
    int sum = 0;
    #pragma unroll
    for (int k = 0; k < CELLS_PER_T; k++) { cnt[k] = g_hist[bs][base + k]; sum += cnt[k]; }
    sh[t] = sum;
    __syncthreads();
    for (int off = 1; off < SCAN_T; off <<= 1) {
        int v = (t >= off) ? sh[t - off] : 0;
        __syncthreads();
        sh[t] += v;
        __syncthreads();
    }
    int run = sh[t] - sum;
    #pragma unroll
    for (int k = 0; k < CELLS_PER_T; k++) {
        g_cellStart[bs][base + k] = run;
        g_writePtr[bs][base + k]  = run;
        run += cnt[k];
    }
    if (t == SCAN_T - 1) g_cellStart[bs][G3] = run;   // == NPTS
}

// ---- k4: scatter points into cell-sorted order ----
__global__ void k4_scatter(const float* __restrict__ a, const float* __restrict__ b) {
    int idx = blockIdx.x * blockDim.x + threadIdx.x;
    if (idx >= NPT_ALL) return;
    GridP g = grid_params();
    int bs = idx >> 13, i = idx & (NPTS - 1);
    const float* p = pt_ptr(a, b, bs, i);
    float x = p[0], y = p[1], z = p[2];
    int cx = cclamp((int)((x - g.lox) * g.inv_h));
    int cy = cclamp((int)((y - g.loy) * g.inv_h));
    int cz = cclamp((int)((z - g.loz) * g.inv_h));
    int pos = atomicAdd(&g_writePtr[bs][(cz * G + cy) * G + cx], 1);
    g_sorted[(bs << 13) + pos] = make_float4(x, y, z, 0.0f);
}

__device__ __forceinline__ void scan_span(const float4* __restrict__ refp,
                                          int s, int e, float4 q, float& best) {
    for (int j = s; j < e; j++) {
        float4 r = refp[j];
        float dx = q.x - r.x, dy = q.y - r.y, dz = q.z - r.z;
        float d = dx * dx;
        d = fmaf(dy, dy, d);
        d = fmaf(dz, dz, d);
        best = fminf(best, d);
    }
}

// ---- k5: exact NN via expanding Chebyshev rings ----
__global__ __launch_bounds__(128)
void k5_query() {
    int qid = blockIdx.x * blockDim.x + threadIdx.x;   // < 65536
    GridP g = grid_params();

    int bs = qid >> 13;
    int ref_bs = bs ^ 1;                               // other side, same batch
    float4 q = g_sorted[qid];
    int qx = cclamp((int)((q.x - g.lox) * g.inv_h));
    int qy = cclamp((int)((q.y - g.loy) * g.inv_h));
    int qz = cclamp((int)((q.z - g.loz) * g.inv_h));

    const float4* refp = g_sorted + (ref_bs << 13);
    const int*    cs   = g_cellStart[ref_bs];

    float best = 3.4e38f;

    for (int m = 0; m < G; m++) {
        if (m >= 1) {
            // all unscanned points are at coordinate distance > (m-1)*h
            float bnd = (float)(m - 1) * g.h * 0.9999f;
            if (best <= bnd * bnd) break;
        }
        int zlo = max(qz - m, 0), zhi = min(qz + m, G - 1);
        int ylo = max(qy - m, 0), yhi = min(qy + m, G - 1);
        int xlo = max(qx - m, 0), xhi = min(qx + m, G - 1);
        for (int cz = zlo; cz <= zhi; cz++) {
            bool zface = (cz == qz - m) || (cz == qz + m);
            for (int cy = ylo; cy <= yhi; cy++) {
                bool yface = (cy == qy - m) || (cy == qy + m);
                int rowbase = (cz * G + cy) * G;
                if (zface || yface) {
                    // full x-run: contiguous cells -> one contiguous point span
                    scan_span(refp, cs[rowbase + xlo], cs[rowbase + xhi + 1], q, best);
                } else {
                    int cxl = qx - m;
                    if (cxl >= 0)
                        scan_span(refp, cs[rowbase + cxl], cs[rowbase + cxl + 1], q, best);
                    int cxr = qx + m;
                    if (cxr <= G - 1)
                        scan_span(refp, cs[rowbase + cxr], cs[rowbase + cxr + 1], q, best);
                }
            }
        }
    }

    // warp sum, then one atomic per warp
    #pragma unroll
    for (int off = 16; off > 0; off >>= 1)
        best += __shfl_xor_sync(0xFFFFFFFFu, best, off);
    if ((threadIdx.x & 31) == 0) atomicAdd(&g_acc, best);
}

__global__ void k6_final(float* __restrict__ out) {
    out[0] = g_acc * (1.0f / (float)(BATCH * NPTS));
}

extern "C" void kernel_launch(void* const* d_in, const int* in_sizes, int n_in,
                              void* d_out, int out_size) {
    const float* a = (const float*)d_in[0];
    const float* b = (const float*)d_in[1];

    k0_init<<<64, 1024>>>();
    k1_bbox<<<64, 256>>>(a, b);
    k2_hist<<<NPT_ALL / 256, 256>>>(a, b);
    k3_scan<<<NSETS, SCAN_T>>>();
    k4_scatter<<<NPT_ALL / 256, 256>>>(a, b);
    k5_query<<<NPT_ALL / 128, 128>>>();
    k6_final<<<1, 1>>>((float*)d_out);
}

// round 8
// speedup vs baseline: 1.2239x; 1.2239x over previous
#include <cuda_runtime.h>
#include <cstdint>

#define BATCH 4
#define NPTS  8192
#define NSETS 8                    // index = batch*2 + side (side 0 = a, 1 = b)
#define NPT_ALL (NSETS * NPTS)     // 65536
#define G  32
#define G3 (G * G * G)
#define NTILES 32                  // G3 / 1024 scan tiles per set
#define CSROW (G3 + 4)             // padded row: keeps every row 16B-aligned

// ---- static scratch (re-initialized every launch sequence) ----
__device__ unsigned int g_bmin[3], g_bmax[3];
__device__ int    g_hist[NSETS][G3];
__device__ int    g_cellStart[NSETS][CSROW];   // [G3] = sentinel (NPTS)
__device__ int    g_writePtr[NSETS][G3];
__device__ int    g_tileSum[NSETS][NTILES];
__device__ int    g_tileOff[NSETS][NTILES];
__device__ float4 g_sorted[NPT_ALL];           // cell-sorted points
__device__ float  g_accArr[64];

// order-preserving float<->uint encoding for atomic min/max
__device__ __forceinline__ unsigned int enc(float f) {
    unsigned int u = __float_as_uint(f);
    return (u & 0x80000000u) ? ~u : (u | 0x80000000u);
}
__device__ __forceinline__ float dec(unsigned int u) {
    return __uint_as_float((u & 0x80000000u) ? (u & 0x7FFFFFFFu) : ~u);
}

struct GridP { float lox, loy, loz, inv_h, h; };
__device__ __forceinline__ GridP grid_params() {
    GridP g;
    g.lox = dec(g_bmin[0]); g.loy = dec(g_bmin[1]); g.loz = dec(g_bmin[2]);
    float ex = dec(g_bmax[0]) - g.lox;
    float ey = dec(g_bmax[1]) - g.loy;
    float ez = dec(g_bmax[2]) - g.loz;
    float e = fmaxf(ex, fmaxf(ey, ez)) * (1.0f + 1e-5f);
    g.h = e / (float)G;
    g.inv_h = (float)G / e;
    return g;
}
__device__ __forceinline__ int cclamp(int v) { return min(max(v, 0), G - 1); }

__device__ __forceinline__ const float* pt_ptr(const float* a, const float* b, int bs, int i) {
    const float* base = (bs & 1) ? b : a;
    return base + ((size_t)((bs >> 1) * NPTS + i)) * 3;
}

// ---- k0: zero hist, sentinels, accumulators ----
__global__ void k0_init() {
    int i = blockIdx.x * blockDim.x + threadIdx.x;
    int stride = gridDim.x * blockDim.x;
    for (int j = i; j < NSETS * G3; j += stride) ((int*)g_hist)[j] = 0;
    if (i < 3)  { g_bmin[i] = 0xFFFFFFFFu; g_bmax[i] = 0u; }
    if (i < 64) g_accArr[i] = 0.0f;
    if (i < NSETS) g_cellStart[i][G3] = NPTS;   // sentinel
}

// ---- k1: global per-axis bbox over both clouds ----
__global__ void k1_bbox(const float* __restrict__ a, const float* __restrict__ b) {
    __shared__ unsigned int smin[3], smax[3];
    if (threadIdx.x < 3) { smin[threadIdx.x] = 0xFFFFFFFFu; smax[threadIdx.x] = 0u; }
    __syncthreads();
    const int total = BATCH * NPTS * 3;
    int i = blockIdx.x * blockDim.x + threadIdx.x;
    int stride = gridDim.x * blockDim.x;
    unsigned int lmin[3] = {0xFFFFFFFFu, 0xFFFFFFFFu, 0xFFFFFFFFu};
    unsigned int lmax[3] = {0u, 0u, 0u};
    for (int j = i; j < 2 * total; j += stride) {
        float v = (j < total) ? a[j] : b[j - total];
        int axis = j % 3;
        unsigned int e = enc(v);
        lmin[axis] = min(lmin[axis], e);
        lmax[axis] = max(lmax[axis], e);
    }
    #pragma unroll
    for (int ax = 0; ax < 3; ax++) {
        atomicMin(&smin[ax], lmin[ax]);
        atomicMax(&smax[ax], lmax[ax]);
    }
    __syncthreads();
    if (threadIdx.x < 3) {
        atomicMin(&g_bmin[threadIdx.x], smin[threadIdx.x]);
        atomicMax(&g_bmax[threadIdx.x], smax[threadIdx.x]);
    }
}

// ---- k2: histogram of cell occupancy ----
__global__ void k2_hist(const float* __restrict__ a, const float* __restrict__ b) {
    int idx = blockIdx.x * blockDim.x + threadIdx.x;
    if (idx >= NPT_ALL) return;
    GridP g = grid_params();
    int bs = idx >> 13, i = idx & (NPTS - 1);
    const float* p = pt_ptr(a, b, bs, i);
    int cx = cclamp((int)((p[0] - g.lox) * g.inv_h));
    int cy = cclamp((int)((p[1] - g.loy) * g.inv_h));
    int cz = cclamp((int)((p[2] - g.loz) * g.inv_h));
    atomicAdd(&g_hist[bs][(cz * G + cy) * G + cx], 1);
}

// ---- k3a: per-tile exclusive scan (coalesced, shfl-based) ----
// grid = NSETS*NTILES CTAs x 256 threads; each thread owns 4 consecutive cells.
__global__ __launch_bounds__(256)
void k3a_tilescan() {
    __shared__ int wsum[8];
    int set  = blockIdx.x >> 5;
    int tile = blockIdx.x & 31;
    int t = threadIdx.x, lane = t & 31, warp = t >> 5;
    int cell = tile * 1024 + t * 4;

    int4 c = *(const int4*)&g_hist[set][cell];
    int s4 = c.x + c.y + c.z + c.w;

    int v = s4;                              // warp inclusive scan
    #pragma unroll
    for (int off = 1; off < 32; off <<= 1) {
        int u = __shfl_up_sync(0xFFFFFFFFu, v, off);
        if (lane >= off) v += u;
    }
    if (lane == 31) wsum[warp] = v;
    __syncthreads();
    if (t == 0) {
        int run = 0;
        #pragma unroll
        for (int w = 0; w < 8; w++) { int x = wsum[w]; wsum[w] = run; run += x; }
    }
    __syncthreads();

    int excl = v - s4 + wsum[warp];          // tile-local exclusive prefix
    int4 p;
    p.x = excl; p.y = p.x + c.x; p.z = p.y + c.y; p.w = p.z + c.z;
    *(int4*)&g_cellStart[set][cell] = p;     // CSROW stride keeps this 16B-aligned
    if (t == 255) g_tileSum[set][tile] = excl + s4;
}

// ---- k3b: scan tile sums (one warp per set) ----
__global__ void k3b_tileoff() {
    int set = threadIdx.x >> 5, lane = threadIdx.x & 31;
    int v = g_tileSum[set][lane];
    int incl = v;
    #pragma unroll
    for (int off = 1; off < 32; off <<= 1) {
        int u = __shfl_up_sync(0xFFFFFFFFu, incl, off);
        if (lane >= off) incl += u;
    }
    g_tileOff[set][lane] = incl - v;
}

// ---- k3c: add tile offsets, fill write pointers ----
__global__ __launch_bounds__(256)
void k3c_finalize() {
    int set  = blockIdx.x >> 5;
    int tile = blockIdx.x & 31;
    int cell = tile * 1024 + threadIdx.x * 4;
    int off  = g_tileOff[set][tile];
    int4 p = *(const int4*)&g_cellStart[set][cell];
    p.x += off; p.y += off; p.z += off; p.w += off;
    *(int4*)&g_cellStart[set][cell] = p;
    *(int4*)&g_writePtr[set][cell]  = p;
}

// ---- k4: scatter points into cell-sorted order ----
__global__ void k4_scatter(const float* __restrict__ a, const float* __restrict__ b) {
    int idx = blockIdx.x * blockDim.x + threadIdx.x;
    if (idx >= NPT_ALL) return;
    GridP g = grid_params();
    int bs = idx >> 13, i = idx & (NPTS - 1);
    const float* p = pt_ptr(a, b, bs, i);
    float x = p[0], y = p[1], z = p[2];
    int cx = cclamp((int)((x - g.lox) * g.inv_h));
    int cy = cclamp((int)((y - g.loy) * g.inv_h));
    int cz = cclamp((int)((z - g.loz) * g.inv_h));
    int pos = atomicAdd(&g_writePtr[bs][(cz * G + cy) * G + cx], 1);
    g_sorted[(bs << 13) + pos] = make_float4(x, y, z, 0.0f);
}

// warp-cooperative span scan: lanes stride the contiguous point run
__device__ __forceinline__ void wscan(const float4* __restrict__ refp,
                                      int s, int e, int lane,
                                      float qx, float qy, float qz, float& best) {
    for (int j = s + lane; j < e; j += 32) {
        float4 r = refp[j];
        float dx = qx - r.x, dy = qy - r.y, dz = qz - r.z;
        float d = dx * dx;
        d = fmaf(dy, dy, d);
        d = fmaf(dz, dz, d);
        best = fminf(best, d);
    }
}
__device__ __forceinline__ float warp_min(float v) {
    #pragma unroll
    for (int off = 16; off > 0; off >>= 1)
        v = fminf(v, __shfl_xor_sync(0xFFFFFFFFu, v, off));
    return v;
}

// ---- k5: exact NN, ONE WARP PER QUERY (uniform control flow) ----
__global__ __launch_bounds__(128)
void k5_query() {
    __shared__ float ws[4];
    int gwid = (blockIdx.x * blockDim.x + threadIdx.x) >> 5;   // query id
    int lane = threadIdx.x & 31;
    GridP g = grid_params();

    int bs = gwid >> 13;
    int ref_bs = bs ^ 1;
    float4 q = g_sorted[gwid];
    int qx = cclamp((int)((q.x - g.lox) * g.inv_h));
    int qy = cclamp((int)((q.y - g.loy) * g.inv_h));
    int qz = cclamp((int)((q.z - g.loz) * g.inv_h));

    const float4* refp = g_sorted + (ref_bs << 13);
    const int*    cs   = g_cellStart[ref_bs];

    float best = 3.4e38f;

    // --- 3x3x3 box around query cell (covers rings m=0,1) ---
    {
        int zlo = max(qz - 1, 0), zhi = min(qz + 1, G - 1);
        int ylo = max(qy - 1, 0), yhi = min(qy + 1, G - 1);
        int xlo = max(qx - 1, 0), xhi = min(qx + 1, G - 1);
        for (int cz = zlo; cz <= zhi; cz++)
            for (int cy = ylo; cy <= yhi; cy++) {
                int rowbase = (cz * G + cy) * G;
                wscan(refp, cs[rowbase + xlo], cs[rowbase + xhi + 1], lane,
                      q.x, q.y, q.z, best);
            }
    }
    best = warp_min(best);

    // --- rare continuation: rings m >= 2, exact stop bound ---
    for (int m = 2; m < G; m++) {
        float bnd = (float)(m - 1) * g.h * 0.9999f;
        if (best <= bnd * bnd) break;
        float pb = best;
        int zlo = max(qz - m, 0), zhi = min(qz + m, G - 1);
        int ylo = max(qy - m, 0), yhi = min(qy + m, G - 1);
        int xlo = max(qx - m, 0), xhi = min(qx + m, G - 1);
        for (int cz = zlo; cz <= zhi; cz++) {
            bool zface = (cz == qz - m) || (cz == qz + m);
            for (int cy = ylo; cy <= yhi; cy++) {
                bool yface = (cy == qy - m) || (cy == qy + m);
                int rowbase = (cz * G + cy) * G;
                if (zface || yface) {
                    wscan(refp, cs[rowbase + xlo], cs[rowbase + xhi + 1], lane,
                          q.x, q.y, q.z, pb);
                } else {
                    int cxl = qx - m;
                    if (cxl >= 0)
                        wscan(refp, cs[rowbase + cxl], cs[rowbase + cxl + 1], lane,
                              q.x, q.y, q.z, pb);
                    int cxr = qx + m;
                    if (cxr <= G - 1)
                        wscan(refp, cs[rowbase + cxr], cs[rowbase + cxr + 1], lane,
                              q.x, q.y, q.z, pb);
                }
            }
        }
        best = warp_min(pb);
    }

    // CTA-level sum (4 warps) then one spread atomic per CTA
    if (lane == 0) ws[threadIdx.x >> 5] = best;
    __syncthreads();
    if (threadIdx.x == 0) {
        float s = ws[0] + ws[1] + ws[2] + ws[3];
        atomicAdd(&g_accArr[blockIdx.x & 63], s);
    }
}

__global__ void k6_final(float* __restrict__ out) {
    __shared__ float red[64];
    red[threadIdx.x] = g_accArr[threadIdx.x];
    __syncthreads();
    #pragma unroll
    for (int s = 32; s > 0; s >>= 1) {
        if (threadIdx.x < s) red[threadIdx.x] += red[threadIdx.x + s];
        __syncthreads();
    }
    if (threadIdx.x == 0) out[0] = red[0] * (1.0f / (float)(BATCH * NPTS));
}

extern "C" void kernel_launch(void* const* d_in, const int* in_sizes, int n_in,
                              void* d_out, int out_size) {
    const float* a = (const float*)d_in[0];
    const float* b = (const float*)d_in[1];

    k0_init<<<64, 1024>>>();
    k1_bbox<<<64, 256>>>(a, b);
    k2_hist<<<NPT_ALL / 256, 256>>>(a, b);
    k3a_tilescan<<<NSETS * NTILES, 256>>>();
    k3b_tileoff<<<1, NSETS * 32>>>();
    k3c_finalize<<<NSETS * NTILES, 256>>>();
    k4_scatter<<<NPT_ALL / 256, 256>>>(a, b);
    k5_query<<<NPT_ALL * 32 / 128, 128>>>();   // one warp per query
    k6_final<<<1, 64>>>((float*)d_out);
}

// round 9
// speedup vs baseline: 3.4192x; 2.7936x over previous
#include <cuda_runtime.h>
#include <cstdint>

#define BATCH 4
#define NPTS  8192
#define NSETS 8                    // index = batch*2 + side (side 0 = a, 1 = b)
#define NPT_ALL (NSETS * NPTS)     // 65536
#define G  32
#define G3 (G * G * G)
#define NTILES 32                  // G3 / 1024 scan tiles per set
#define CSROW (G3 + 4)             // padded row: keeps every row 16B-aligned

// ---- static scratch (re-initialized every launch sequence) ----
__device__ unsigned int g_bmin[3], g_bmax[3];
__device__ int    g_hist[NSETS][G3];
__device__ int    g_cellStart[NSETS][CSROW];   // [G3] = sentinel (NPTS)
__device__ int    g_writePtr[NSETS][G3];
__device__ int    g_tileSum[NSETS][NTILES];
__device__ int    g_tileOff[NSETS][NTILES];
__device__ float4 g_sorted[NPT_ALL];           // cell-sorted points
__device__ float  g_accArr[64];

// order-preserving float<->uint encoding for atomic min/max
__device__ __forceinline__ unsigned int enc(float f) {
    unsigned int u = __float_as_uint(f);
    return (u & 0x80000000u) ? ~u : (u | 0x80000000u);
}
__device__ __forceinline__ float dec(unsigned int u) {
    return __uint_as_float((u & 0x80000000u) ? (u & 0x7FFFFFFFu) : ~u);
}

struct GridP { float lox, loy, loz, inv_h, h; };
__device__ __forceinline__ GridP grid_params() {
    GridP g;
    g.lox = dec(g_bmin[0]); g.loy = dec(g_bmin[1]); g.loz = dec(g_bmin[2]);
    float ex = dec(g_bmax[0]) - g.lox;
    float ey = dec(g_bmax[1]) - g.loy;
    float ez = dec(g_bmax[2]) - g.loz;
    float e = fmaxf(ex, fmaxf(ey, ez)) * (1.0f + 1e-5f);
    g.h = e / (float)G;
    g.inv_h = (float)G / e;
    return g;
}
__device__ __forceinline__ int cclamp(int v) { return min(max(v, 0), G - 1); }

__device__ __forceinline__ const float* pt_ptr(const float* a, const float* b, int bs, int i) {
    const float* base = (bs & 1) ? b : a;
    return base + ((size_t)((bs >> 1) * NPTS + i)) * 3;
}

// ---- k0: zero hist, sentinels, accumulators ----
__global__ void k0_init() {
    int i = blockIdx.x * blockDim.x + threadIdx.x;
    int stride = gridDim.x * blockDim.x;
    for (int j = i; j < NSETS * G3; j += stride) ((int*)g_hist)[j] = 0;
    if (i < 3)  { g_bmin[i] = 0xFFFFFFFFu; g_bmax[i] = 0u; }
    if (i < 64) g_accArr[i] = 0.0f;
    if (i < NSETS) g_cellStart[i][G3] = NPTS;   // sentinel
}

// ---- k1: global per-axis bbox over both clouds ----
__global__ void k1_bbox(const float* __restrict__ a, const float* __restrict__ b) {
    __shared__ unsigned int smin[3], smax[3];
    if (threadIdx.x < 3) { smin[threadIdx.x] = 0xFFFFFFFFu; smax[threadIdx.x] = 0u; }
    __syncthreads();
    const int total = BATCH * NPTS * 3;
    int i = blockIdx.x * blockDim.x + threadIdx.x;
    int stride = gridDim.x * blockDim.x;
    unsigned int lmin[3] = {0xFFFFFFFFu, 0xFFFFFFFFu, 0xFFFFFFFFu};
    unsigned int lmax[3] = {0u, 0u, 0u};
    for (int j = i; j < 2 * total; j += stride) {
        float v = (j < total) ? a[j] : b[j - total];
        int axis = j % 3;
        unsigned int e = enc(v);
        lmin[axis] = min(lmin[axis], e);
        lmax[axis] = max(lmax[axis], e);
    }
    #pragma unroll
    for (int ax = 0; ax < 3; ax++) {
        atomicMin(&smin[ax], lmin[ax]);
        atomicMax(&smax[ax], lmax[ax]);
    }
    __syncthreads();
    if (threadIdx.x < 3) {
        atomicMin(&g_bmin[threadIdx.x], smin[threadIdx.x]);
        atomicMax(&g_bmax[threadIdx.x], smax[threadIdx.x]);
    }
}

// ---- k2: histogram of cell occupancy ----
__global__ void k2_hist(const float* __restrict__ a, const float* __restrict__ b) {
    int idx = blockIdx.x * blockDim.x + threadIdx.x;
    if (idx >= NPT_ALL) return;
    GridP g = grid_params();
    int bs = idx >> 13, i = idx & (NPTS - 1);
    const float* p = pt_ptr(a, b, bs, i);
    int cx = cclamp((int)((p[0] - g.lox) * g.inv_h));
    int cy = cclamp((int)((p[1] - g.loy) * g.inv_h));
    int cz = cclamp((int)((p[2] - g.loz) * g.inv_h));
    atomicAdd(&g_hist[bs][(cz * G + cy) * G + cx], 1);
}

// ---- k3a: per-tile exclusive scan (coalesced, shfl-based) ----
__global__ __launch_bounds__(256)
void k3a_tilescan() {
    __shared__ int wsum[8];
    int set  = blockIdx.x >> 5;
    int tile = blockIdx.x & 31;
    int t = threadIdx.x, lane = t & 31, warp = t >> 5;
    int cell = tile * 1024 + t * 4;

    int4 c = *(const int4*)&g_hist[set][cell];
    int s4 = c.x + c.y + c.z + c.w;

    int v = s4;
    #pragma unroll
    for (int off = 1; off < 32; off <<= 1) {
        int u = __shfl_up_sync(0xFFFFFFFFu, v, off);
        if (lane >= off) v += u;
    }
    if (lane == 31) wsum[warp] = v;
    __syncthreads();
    if (t == 0) {
        int run = 0;
        #pragma unroll
        for (int w = 0; w < 8; w++) { int x = wsum[w]; wsum[w] = run; run += x; }
    }
    __syncthreads();

    int excl = v - s4 + wsum[warp];
    int4 p;
    p.x = excl; p.y = p.x + c.x; p.z = p.y + c.y; p.w = p.z + c.z;
    *(int4*)&g_cellStart[set][cell] = p;
    if (t == 255) g_tileSum[set][tile] = excl + s4;
}

// ---- k3b: scan tile sums (one warp per set) ----
__global__ void k3b_tileoff() {
    int set = threadIdx.x >> 5, lane = threadIdx.x & 31;
    int v = g_tileSum[set][lane];
    int incl = v;
    #pragma unroll
    for (int off = 1; off < 32; off <<= 1) {
        int u = __shfl_up_sync(0xFFFFFFFFu, incl, off);
        if (lane >= off) incl += u;
    }
    g_tileOff[set][lane] = incl - v;
}

// ---- k3c: add tile offsets, fill write pointers ----
__global__ __launch_bounds__(256)
void k3c_finalize() {
    int set  = blockIdx.x >> 5;
    int tile = blockIdx.x & 31;
    int cell = tile * 1024 + threadIdx.x * 4;
    int off  = g_tileOff[set][tile];
    int4 p = *(const int4*)&g_cellStart[set][cell];
    p.x += off; p.y += off; p.z += off; p.w += off;
    *(int4*)&g_cellStart[set][cell] = p;
    *(int4*)&g_writePtr[set][cell]  = p;
}

// ---- k4: scatter points into cell-sorted order ----
__global__ void k4_scatter(const float* __restrict__ a, const float* __restrict__ b) {
    int idx = blockIdx.x * blockDim.x + threadIdx.x;
    if (idx >= NPT_ALL) return;
    GridP g = grid_params();
    int bs = idx >> 13, i = idx & (NPTS - 1);
    const float* p = pt_ptr(a, b, bs, i);
    float x = p[0], y = p[1], z = p[2];
    int cx = cclamp((int)((x - g.lox) * g.inv_h));
    int cy = cclamp((int)((y - g.loy) * g.inv_h));
    int cz = cclamp((int)((z - g.loz) * g.inv_h));
    int pos = atomicAdd(&g_writePtr[bs][(cz * G + cy) * G + cx], 1);
    g_sorted[(bs << 13) + pos] = make_float4(x, y, z, 0.0f);
}

__device__ __forceinline__ float warp_min(float v) {
    #pragma unroll
    for (int off = 16; off > 0; off >>= 1)
        v = fminf(v, __shfl_xor_sync(0xFFFFFFFFu, v, off));
    return v;
}

// ---- k5: exact NN, warp per query, LANE-PARALLEL cell scanning ----
// Radius-1 box: lane-per-cell (27 parallel cells, one latency batch).
// Rings m>=2: full-box rescan with lane-per-row (parallel latency batches).
// Stop bound: after scanning box radius m, unscanned points are >= m*h away.
__global__ __launch_bounds__(128)
void k5_query() {
    __shared__ float ws[4];
    int gwid = (blockIdx.x * blockDim.x + threadIdx.x) >> 5;   // query id
    int lane = threadIdx.x & 31;
    GridP g = grid_params();

    int bs = gwid >> 13;
    int ref_bs = bs ^ 1;
    float4 q = g_sorted[gwid];
    int qx = cclamp((int)((q.x - g.lox) * g.inv_h));
    int qy = cclamp((int)((q.y - g.loy) * g.inv_h));
    int qz = cclamp((int)((q.z - g.loz) * g.inv_h));

    const float4* refp = g_sorted + (ref_bs << 13);
    const int*    cs   = g_cellStart[ref_bs];

    float best = 3.4e38f;

    // --- radius-1 box: one cell per lane (27 cells) ---
    if (lane < 27) {
        int dz = lane / 9, rem = lane - dz * 9;
        int dy = rem / 3,  dx = rem - dy * 3;
        int cz = qz + dz - 1, cy = qy + dy - 1, cx = qx + dx - 1;
        if (((unsigned)cz < G) & ((unsigned)cy < G) & ((unsigned)cx < G)) {
            int base = (cz * G + cy) * G + cx;
            int s = cs[base], e = cs[base + 1];
            for (int j = s; j < e; j++) {
                float4 r = refp[j];
                float dxf = q.x - r.x, dyf = q.y - r.y, dzf = q.z - r.z;
                float d = dxf * dxf;
                d = fmaf(dyf, dyf, d);
                d = fmaf(dzf, dzf, d);
                best = fminf(best, d);
            }
        }
    }
    best = warp_min(best);

    // --- rare: expand by full-box rescans, lane-per-row ---
    float h99 = g.h * 0.9999f;
    for (int m = 2; m <= G; m++) {
        float bnd = (float)(m - 1) * h99;
        if (best <= bnd * bnd) break;
        float pb = best;
        int W = 2 * m + 1;
        int nrows = W * W;
        int xlo = max(qx - m, 0), xhi = min(qx + m, G - 1);
        for (int r = lane; r < nrows; r += 32) {
            int rz = r / W, ry = r - rz * W;
            int cz = qz - m + rz, cy = qy - m + ry;
            if (((unsigned)cz >= G) | ((unsigned)cy >= G)) continue;
            int rowbase = (cz * G + cy) * G;
            int s = cs[rowbase + xlo], e = cs[rowbase + xhi + 1];
            for (int j = s; j < e; j++) {
                float4 rp = refp[j];
                float dxf = q.x - rp.x, dyf = q.y - rp.y, dzf = q.z - rp.z;
                float d = dxf * dxf;
                d = fmaf(dyf, dyf, d);
                d = fmaf(dzf, dzf, d);
                pb = fminf(pb, d);
            }
        }
        best = warp_min(pb);
    }

    // CTA-level sum (4 warps) then one spread atomic per CTA
    if (lane == 0) ws[threadIdx.x >> 5] = best;
    __syncthreads();
    if (threadIdx.x == 0) {
        float s = ws[0] + ws[1] + ws[2] + ws[3];
        atomicAdd(&g_accArr[blockIdx.x & 63], s);
    }
}

__global__ void k6_final(float* __restrict__ out) {
    __shared__ float red[64];
    red[threadIdx.x] = g_accArr[threadIdx.x];
    __syncthreads();
    #pragma unroll
    for (int s = 32; s > 0; s >>= 1) {
        if (threadIdx.x < s) red[threadIdx.x] += red[threadIdx.x + s];
        __syncthreads();
    }
    if (threadIdx.x == 0) out[0] = red[0] * (1.0f / (float)(BATCH * NPTS));
}

extern "C" void kernel_launch(void* const* d_in, const int* in_sizes, int n_in,
                              void* d_out, int out_size) {
    const float* a = (const float*)d_in[0];
    const float* b = (const float*)d_in[1];

    k0_init<<<64, 1024>>>();
    k1_bbox<<<64, 256>>>(a, b);
    k2_hist<<<NPT_ALL / 256, 256>>>(a, b);
    k3a_tilescan<<<NSETS * NTILES, 256>>>();
    k3b_tileoff<<<1, NSETS * 32>>>();
    k3c_finalize<<<NSETS * NTILES, 256>>>();
    k4_scatter<<<NPT_ALL / 256, 256>>>(a, b);
    k5_query<<<NPT_ALL * 32 / 128, 128>>>();   // one warp per query
    k6_final<<<1, 64>>>((float*)d_out);
}